// round 15
// baseline (speedup 1.0000x reference)
#include <cuda_runtime.h>

// Problem constants
#define NP    196           // patches per image
#define NCG   49            // NP/4 column groups
#define NF4   (NP * NCG)    // 9604 float4 elements in one adj matrix
#define TPB   392           // = 2*196 = 8*49: loads 2 images; stride keeps cg fixed
#define IPC   2             // images per CTA
#define HID   32
#define NCLS  10
#define TSQRT 0.894427191f  // sqrt(0.8)

__device__ __forceinline__ float dot4(float4 a, float4 b) {
    return a.x * b.x + a.y * b.y + a.z * b.z + a.w * b.w;
}

// fid = dot^2 >= 0.8  <=>  |dot| >= sqrt(0.8); FSETP applies |.| for free
__device__ __forceinline__ float classify(float d) {
    return (fabsf(d) >= TSQRT) ? 1.0f : 0.0f;
}

__device__ __forceinline__ void fix_diag(float4& r, int row, int cg) {
    if ((row >> 2) == cg) {
        const int c = row & 3;
        if      (c == 0) r.x = 0.f;
        else if (c == 1) r.y = 0.f;
        else if (c == 2) r.z = 0.f;
        else             r.w = 0.f;
    }
}

// min 3 blocks: hard cap 55 regs so we never fall off the 3-CTA/SM cliff
// (R10 lesson: 56 regs -> only 2 CTAs fit -> occupancy collapse).
__global__ __launch_bounds__(TPB, 3)
void quanv_graph_kernel(const float* __restrict__ x,
                        const float* __restrict__ W1,
                        const float* __restrict__ b1,
                        const float* __restrict__ W2,
                        const float* __restrict__ b2,
                        float* __restrict__ out,
                        float* __restrict__ adj)
{
    __shared__ float4 an_s[IPC][NP];   // normalized vectors, per image
    __shared__ float4 vec_s[IPC][NP];  // raw vectors (for pooling), per image

    const int tid = threadIdx.x;
    const int b0  = blockIdx.x * IPC;  // first image this CTA owns

    // ---- Phase 1: both images' patch expectations in ONE sweep ----
    {
        const int img = (tid >= NP) ? 1 : 0;
        const int p   = tid - img * NP;
        const float4 v = reinterpret_cast<const float4*>(x)[(size_t)(b0 + img) * NP + p];
        float c0 = cosf(v.x + 0.5f);
        float c1 = c0 * cosf(v.y + 0.5f);
        float c2 = c1 * cosf(v.z + 0.5f);
        float c3 = c2 * cosf(v.w + 0.5f);
        vec_s[img][p] = make_float4(c0, c1, c2, c3);
        float n   = sqrtf(c0 * c0 + c1 * c1 + c2 * c2 + c3 * c3);
        float inv = 1.0f / (n + 1e-12f);
        an_s[img][p] = make_float4(c0 * inv, c1 * inv, c2 * inv, c3 * inv);
    }
    __syncthreads();

    const int warp = tid >> 5;
    const int lane = tid & 31;

    // ---- MLP heads: warp 0 -> image 0, warp 1 -> image 1 (lanes 0..9) ----
    if (warp < IPC && lane < NCLS) {
        const int img = warp;
        float px = 0.f, py = 0.f, pz = 0.f, pw = 0.f;
        #pragma unroll 4
        for (int p = 0; p < NP; ++p) {
            float4 v = vec_s[img][p];   // warp-uniform address -> broadcast
            px += v.x; py += v.y; pz += v.z; pw += v.w;
        }
        const float s = 1.0f / (float)NP;
        px *= s; py *= s; pz *= s; pw *= s;
        float acc = b2[lane];
        #pragma unroll 4
        for (int h = 0; h < HID; ++h) {
            float hh = b1[h] + px * W1[h * 4 + 0] + py * W1[h * 4 + 1]
                             + pz * W1[h * 4 + 2] + pw * W1[h * 4 + 3];
            acc += hh * W2[lane * HID + h];
        }
        out[(size_t)(b0 + img) * NCLS + lane] = acc;
    }

    // ---- Phase 2: adjacency, 4x unrolled flat loop per image ----
    // Thread t owns fixed column group cg = t % 49; one register-resident
    // u-set serves all four streams of each quad-iteration. Four independent
    // LDS + four independent STG.128 per trip -> deep store window, 1/4 the
    // bookkeeping. 6 trips cover 24 iterations (flat < 9408); 196-word tail.
    const int cg    = tid % NCG;
    const int row00 = tid / NCG;      // 0..7

    #pragma unroll
    for (int img = 0; img < IPC; ++img) {
        const float4* an = an_s[img];

        const float4 u0 = an[4 * cg + 0];
        const float4 u1 = an[4 * cg + 1];
        const float4 u2 = an[4 * cg + 2];
        const float4 u3 = an[4 * cg + 3];

        float4* __restrict__ adj4 =
            reinterpret_cast<float4*>(adj + (size_t)(b0 + img) * (NP * NP));

        int row  = row00;
        int flat = tid;
        for (int k = 0; k < 6; ++k) {
            const float4 a0 = an[row];
            const float4 a1 = an[row +  8];
            const float4 a2 = an[row + 16];
            const float4 a3 = an[row + 24];

            float4 r0 = make_float4(classify(dot4(a0, u0)), classify(dot4(a0, u1)),
                                    classify(dot4(a0, u2)), classify(dot4(a0, u3)));
            float4 r1 = make_float4(classify(dot4(a1, u0)), classify(dot4(a1, u1)),
                                    classify(dot4(a1, u2)), classify(dot4(a1, u3)));
            float4 r2 = make_float4(classify(dot4(a2, u0)), classify(dot4(a2, u1)),
                                    classify(dot4(a2, u2)), classify(dot4(a2, u3)));
            float4 r3 = make_float4(classify(dot4(a3, u0)), classify(dot4(a3, u1)),
                                    classify(dot4(a3, u2)), classify(dot4(a3, u3)));

            fix_diag(r0, row,      cg);
            fix_diag(r1, row +  8, cg);
            fix_diag(r2, row + 16, cg);
            fix_diag(r3, row + 24, cg);

            __stcs(adj4 + flat,           r0);   // 4 independent stores
            __stcs(adj4 + flat +     TPB, r1);
            __stcs(adj4 + flat + 2 * TPB, r2);
            __stcs(adj4 + flat + 3 * TPB, r3);
            flat += 4 * TPB;
            row  += 32;
        }
        // tail: 9604 - 9408 = 196 words -> threads 0..195
        if (flat < NF4) {
            const float4 a = an[row];
            float4 r = make_float4(classify(dot4(a, u0)), classify(dot4(a, u1)),
                                   classify(dot4(a, u2)), classify(dot4(a, u3)));
            fix_diag(r, row, cg);
            __stcs(adj4 + flat, r);
        }
    }
}

extern "C" void kernel_launch(void* const* d_in, const int* in_sizes, int n_in,
                              void* d_out, int out_size)
{
    const float* x  = (const float*)d_in[0];   // [B,1,28,28]
    const float* W1 = (const float*)d_in[1];   // [32,4]
    const float* b1 = (const float*)d_in[2];   // [32]
    const float* W2 = (const float*)d_in[3];   // [10,32]
    const float* b2 = (const float*)d_in[4];   // [10]

    const int B = in_sizes[0] / 784;           // 4096

    float* out = (float*)d_out;                // [B,10] first
    float* adj = (float*)d_out + (size_t)B * NCLS;  // then [B,196,196]

    quanv_graph_kernel<<<B / IPC, TPB>>>(x, W1, b1, W2, b2, out, adj);
}

// round 16
// speedup vs baseline: 1.0350x; 1.0350x over previous
#include <cuda_runtime.h>

// Problem constants
#define NP    196           // patches per image
#define NCG   49            // NP/4 column groups
#define NF4   (NP * NCG)    // 9604 float4 elements in one adj matrix
#define TPB   392           // = 2*196 = 8*49: loads 2 images; stride keeps cg fixed
#define IPC   2             // images per CTA
#define HID   32
#define NCLS  10
#define TSQRT 0.894427191f  // sqrt(0.8)

__device__ __forceinline__ float dot4(float4 a, float4 b) {
    return a.x * b.x + a.y * b.y + a.z * b.z + a.w * b.w;
}

// fid = dot^2 >= 0.8  <=>  |dot| >= sqrt(0.8); FSETP applies |.| for free
__device__ __forceinline__ float classify(float d) {
    return (fabsf(d) >= TSQRT) ? 1.0f : 0.0f;
}

__global__ __launch_bounds__(TPB, 2)
void quanv_graph_kernel(const float* __restrict__ x,
                        const float* __restrict__ W1,
                        const float* __restrict__ b1,
                        const float* __restrict__ W2,
                        const float* __restrict__ b2,
                        float* __restrict__ out,
                        float* __restrict__ adj)
{
    __shared__ float4 an_s[IPC][NP];   // normalized vectors, per image
    __shared__ float4 vec_s[IPC][NP];  // raw vectors (for pooling), per image

    const int tid = threadIdx.x;
    const int b0  = blockIdx.x * IPC;  // first image this CTA owns

    // ---- Phase 1: both images' patch expectations in ONE sweep ----
    // tid 0..195 -> image 0 patch tid; tid 196..391 -> image 1 patch tid-196.
    {
        const int img = (tid >= NP) ? 1 : 0;
        const int p   = tid - img * NP;
        const float4 v = reinterpret_cast<const float4*>(x)[(size_t)(b0 + img) * NP + p];
        float c0 = cosf(v.x + 0.5f);
        float c1 = c0 * cosf(v.y + 0.5f);
        float c2 = c1 * cosf(v.z + 0.5f);
        float c3 = c2 * cosf(v.w + 0.5f);
        vec_s[img][p] = make_float4(c0, c1, c2, c3);
        float n   = sqrtf(c0 * c0 + c1 * c1 + c2 * c2 + c3 * c3);
        float inv = 1.0f / (n + 1e-12f);
        an_s[img][p] = make_float4(c0 * inv, c1 * inv, c2 * inv, c3 * inv);
    }
    __syncthreads();

    const int warp = tid >> 5;
    const int lane = tid & 31;

    // ---- MLP heads: warp 0 -> image 0, warp 1 -> image 1 (lanes 0..9) ----
    if (warp < IPC && lane < NCLS) {
        const int img = warp;
        float px = 0.f, py = 0.f, pz = 0.f, pw = 0.f;
        #pragma unroll 4
        for (int p = 0; p < NP; ++p) {
            float4 v = vec_s[img][p];   // warp-uniform address -> broadcast
            px += v.x; py += v.y; pz += v.z; pw += v.w;
        }
        const float s = 1.0f / (float)NP;
        px *= s; py *= s; pz *= s; pw *= s;
        float acc = b2[lane];
        #pragma unroll 4
        for (int h = 0; h < HID; ++h) {
            float hh = b1[h] + px * W1[h * 4 + 0] + py * W1[h * 4 + 1]
                             + pz * W1[h * 4 + 2] + pw * W1[h * 4 + 3];
            acc += hh * W2[lane * HID + h];
        }
        out[(size_t)(b0 + img) * NCLS + lane] = acc;
    }

    // ---- Phase 2: adjacency for both images (flat-indexed hot loop) ----
    // Thread t owns fixed column group cg = t % 49 (u-vectors register-
    // resident). Flat float4 index advances by 392 = 8*49 per iteration, so
    // cg never changes and row += 8. Every warp's 32 lanes store 32
    // consecutive float4 = one dense 512B run; 100% lane utilization.
    const int cg    = tid % NCG;
    const int row00 = tid / NCG;      // 0..7

    #pragma unroll
    for (int img = 0; img < IPC; ++img) {
        const float4* an = an_s[img];

        const float4 u0 = an[4 * cg + 0];
        const float4 u1 = an[4 * cg + 1];
        const float4 u2 = an[4 * cg + 2];
        const float4 u3 = an[4 * cg + 3];

        float4* __restrict__ adj4 =
            reinterpret_cast<float4*>(adj + (size_t)(b0 + img) * (NP * NP));

        int row = row00;
        for (int flat = tid; flat < NF4; flat += TPB, row += 8) {
            const float4 a = an[row];   // <=2 distinct rows per warp
            float4 r = make_float4(classify(dot4(a, u0)), classify(dot4(a, u1)),
                                   classify(dot4(a, u2)), classify(dot4(a, u3)));
            if ((row >> 2) == cg) {     // self-edge diagonal in this group
                const int c = row & 3;
                if      (c == 0) r.x = 0.f;
                else if (c == 1) r.y = 0.f;
                else if (c == 2) r.z = 0.f;
                else             r.w = 0.f;
            }
            __stcs(adj4 + flat, r);     // evict-first: write-once data
        }
    }
}

extern "C" void kernel_launch(void* const* d_in, const int* in_sizes, int n_in,
                              void* d_out, int out_size)
{
    const float* x  = (const float*)d_in[0];   // [B,1,28,28]
    const float* W1 = (const float*)d_in[1];   // [32,4]
    const float* b1 = (const float*)d_in[2];   // [32]
    const float* W2 = (const float*)d_in[3];   // [10,32]
    const float* b2 = (const float*)d_in[4];   // [10]

    const int B = in_sizes[0] / 784;           // 4096

    float* out = (float*)d_out;                // [B,10] first
    float* adj = (float*)d_out + (size_t)B * NCLS;  // then [B,196,196]

    quanv_graph_kernel<<<B / IPC, TPB>>>(x, W1, b1, W2, b2, out, adj);
}

// round 17
// speedup vs baseline: 1.0533x; 1.0177x over previous
#include <cuda_runtime.h>

// Problem constants
#define NP    196           // patches per image
#define NCG   49            // NP/4 column groups
#define NF4   (NP * NCG)    // 9604 float4 elements in one adj matrix
#define TPB   392           // = 2*196 = 8*49: loads 2 images; stride keeps cg fixed
#define IPC   2             // images per CTA
#define HID   32
#define NCLS  10
#define TSQRT 0.894427191f  // sqrt(0.8)

__device__ __forceinline__ float dot4(float4 a, float4 b) {
    return a.x * b.x + a.y * b.y + a.z * b.z + a.w * b.w;
}

// fid = dot^2 >= 0.8  <=>  |dot| >= sqrt(0.8); FSETP applies |.| for free
__device__ __forceinline__ float classify(float d) {
    return (fabsf(d) >= TSQRT) ? 1.0f : 0.0f;
}

__global__ __launch_bounds__(TPB, 2)
void quanv_graph_kernel(const float* __restrict__ x,
                        const float* __restrict__ W1,
                        const float* __restrict__ b1,
                        const float* __restrict__ W2,
                        const float* __restrict__ b2,
                        float* __restrict__ out,
                        float* __restrict__ adj)
{
    __shared__ float4 an_s[IPC][NP];   // normalized vectors, per image
    __shared__ float4 vec_s[IPC][NP];  // raw vectors (for pooling), per image

    const int tid = threadIdx.x;
    const int b0  = blockIdx.x * IPC;  // first image this CTA owns

    // ---- Phase 1: both images' patch expectations in ONE sweep ----
    // tid 0..195 -> image 0 patch tid; tid 196..391 -> image 1 patch tid-196.
    {
        const int img = (tid >= NP) ? 1 : 0;
        const int p   = tid - img * NP;
        const float4 v = reinterpret_cast<const float4*>(x)[(size_t)(b0 + img) * NP + p];
        float c0 = cosf(v.x + 0.5f);
        float c1 = c0 * cosf(v.y + 0.5f);
        float c2 = c1 * cosf(v.z + 0.5f);
        float c3 = c2 * cosf(v.w + 0.5f);
        vec_s[img][p] = make_float4(c0, c1, c2, c3);
        float n   = sqrtf(c0 * c0 + c1 * c1 + c2 * c2 + c3 * c3);
        float inv = 1.0f / (n + 1e-12f);
        an_s[img][p] = make_float4(c0 * inv, c1 * inv, c2 * inv, c3 * inv);
    }
    __syncthreads();

    const int warp = tid >> 5;
    const int lane = tid & 31;

    // ---- MLP heads: warp 0 -> image 0, warp 1 -> image 1 (lanes 0..9) ----
    if (warp < IPC && lane < NCLS) {
        const int img = warp;
        float px = 0.f, py = 0.f, pz = 0.f, pw = 0.f;
        #pragma unroll 4
        for (int p = 0; p < NP; ++p) {
            float4 v = vec_s[img][p];   // warp-uniform address -> broadcast
            px += v.x; py += v.y; pz += v.z; pw += v.w;
        }
        const float s = 1.0f / (float)NP;
        px *= s; py *= s; pz *= s; pw *= s;
        float acc = b2[lane];
        #pragma unroll 4
        for (int h = 0; h < HID; ++h) {
            float hh = b1[h] + px * W1[h * 4 + 0] + py * W1[h * 4 + 1]
                             + pz * W1[h * 4 + 2] + pw * W1[h * 4 + 3];
            acc += hh * W2[lane * HID + h];
        }
        out[(size_t)(b0 + img) * NCLS + lane] = acc;
    }

    // ---- Phase 2: adjacency for both images (flat-indexed hot loop) ----
    // Thread t owns fixed column group cg = t % 49 (u-vectors register-
    // resident). Flat float4 index advances by 392 = 8*49 per iteration, so
    // cg never changes and row += 8. Every warp's 32 lanes store 32
    // consecutive float4 = one dense 512B run; 100% lane utilization.
    const int cg    = tid % NCG;
    const int row00 = tid / NCG;      // 0..7

    // Each thread meets its diagonal block on AT MOST ONE row of its sweep:
    // rows visited are row00 (mod 8); the diagonal needs row in [4cg, 4cg+3].
    // Precompute that row (or -1) so the in-loop test is a single compare.
    int diag_row = -1, diag_c = 0;
    {
        const int base = 4 * cg;
        const int off  = (row00 - base) & 7;   // row00 mod 8 relative to base
        if (off < 4) { diag_row = base + off; diag_c = off & 3; }
    }

    #pragma unroll
    for (int img = 0; img < IPC; ++img) {
        const float4* an = an_s[img];

        const float4 u0 = an[4 * cg + 0];
        const float4 u1 = an[4 * cg + 1];
        const float4 u2 = an[4 * cg + 2];
        const float4 u3 = an[4 * cg + 3];

        float4* __restrict__ adj4 =
            reinterpret_cast<float4*>(adj + (size_t)(b0 + img) * (NP * NP));

        int row = row00;
        for (int flat = tid; flat < NF4; flat += TPB, row += 8) {
            const float4 a = an[row];   // <=2 distinct rows per warp
            float4 r = make_float4(classify(dot4(a, u0)), classify(dot4(a, u1)),
                                   classify(dot4(a, u2)), classify(dot4(a, u3)));
            if (row == diag_row) {      // single ISETP; taken <=1x per sweep
                if      (diag_c == 0) r.x = 0.f;
                else if (diag_c == 1) r.y = 0.f;
                else if (diag_c == 2) r.z = 0.f;
                else                  r.w = 0.f;
            }
            __stcs(adj4 + flat, r);     // evict-first: write-once data
        }
    }
}

extern "C" void kernel_launch(void* const* d_in, const int* in_sizes, int n_in,
                              void* d_out, int out_size)
{
    const float* x  = (const float*)d_in[0];   // [B,1,28,28]
    const float* W1 = (const float*)d_in[1];   // [32,4]
    const float* b1 = (const float*)d_in[2];   // [32]
    const float* W2 = (const float*)d_in[3];   // [10,32]
    const float* b2 = (const float*)d_in[4];   // [10]

    const int B = in_sizes[0] / 784;           // 4096

    float* out = (float*)d_out;                // [B,10] first
    float* adj = (float*)d_out + (size_t)B * NCLS;  // then [B,196,196]

    quanv_graph_kernel<<<B / IPC, TPB>>>(x, W1, b1, W2, b2, out, adj);
}